// round 7
// baseline (speedup 1.0000x reference)
#include <cuda_runtime.h>

// Problem constants (MultiLayerGAT: N=50000, E=800000, IN_F=128, HID=64, HEADS=4)
#define NNODES 50000
#define NEDGES 800000
#define EPRIME (NNODES + NEDGES)   // edges + self loops
#define CF 256                     // HEADS * HID
#define NEG_SLOPE 0.2f
#define NBLK ((NNODES + 1023) / 1024)   // 49 scan blocks

// ---------------- device scratch (no allocations allowed) ----------------
__device__ float g_h[(size_t)NNODES * CF];     // current layer features  (51.2 MB)
__device__ float g_y[(size_t)NNODES * CF];     // layer-1 output          (51.2 MB)
__device__ float g_asrc[NNODES * 4];
__device__ float g_adst[NNODES * 4];
__device__ float g_rcp[NNODES * 4];
__device__ float g_ex[(size_t)EPRIME * 4];     // exp(e - m) per edge/head (13.6 MB)
__device__ int   g_rowptr[NNODES + 1];
__device__ int   g_cursor[NNODES];
__device__ int   g_eid[EPRIME];
__device__ int   g_blocksum[64];
__device__ int   g_flagOr;                     // 0 => edge_index is int64

// ---------------- edge index accessors (int32/int64 agnostic) ----------------
__device__ __forceinline__ int load_src(const void* ei, bool is64, int e) {
    return is64 ? (int)((const long long*)ei)[e] : ((const int*)ei)[e];
}
__device__ __forceinline__ int load_dst(const void* ei, bool is64, int e) {
    return is64 ? (int)((const long long*)ei)[(size_t)NEDGES + e]
                : ((const int*)ei)[(size_t)NEDGES + e];
}

// ---------------- packed f32x2 helpers (FFMA2 — ptxas never auto-emits this) ----
__device__ __forceinline__ unsigned long long bcast_f32x2(float v) {
    unsigned long long d;
    asm("mov.b64 %0, {%1, %1};" : "=l"(d) : "f"(v));
    return d;
}
__device__ __forceinline__ unsigned long long fma_f32x2(
    unsigned long long a, unsigned long long b, unsigned long long c) {
    unsigned long long d;
    asm("fma.rn.f32x2 %0, %1, %2, %3;" : "=l"(d) : "l"(a), "l"(b), "l"(c));
    return d;
}

// ---------------- CSR build ----------------
__global__ void init_kernel() {
    int i = blockIdx.x * blockDim.x + threadIdx.x;
    if (i < NNODES) g_cursor[i] = 1;   // self loop
    if (i == 0) g_flagOr = 0;
}

// OR-reduce the odd 32-bit words of the first E 64-bit slots. If the buffer is
// really int64 (values < 2^31) these are all zero; if it is int32 these words
// are src[1],src[3],... node ids and are virtually certainly nonzero.
__global__ void detect_kernel(const int* __restrict__ ei32) {
    int i = blockIdx.x * blockDim.x + threadIdx.x;
    int stride = gridDim.x * blockDim.x;
    int acc = 0;
    for (; i < NEDGES; i += stride) acc |= ei32[2 * i + 1];
    if (acc) atomicOr(&g_flagOr, 1);
}

__global__ void count_kernel(const void* __restrict__ ei) {
    bool is64 = (g_flagOr == 0);
    int i = blockIdx.x * blockDim.x + threadIdx.x;
    if (i < NEDGES) {
        int d = load_dst(ei, is64, i);
        atomicAdd(&g_cursor[d], 1);
    }
}

// ---- parallel scan, phase A: per-block exclusive scan + block sums ----
__global__ void scanA_kernel() {
    __shared__ int warpsum[32];
    int tid  = threadIdx.x;
    int gid  = blockIdx.x * 1024 + tid;
    int lane = tid & 31, wid = tid >> 5;
    int v = (gid < NNODES) ? g_cursor[gid] : 0;
    int x = v;
#pragma unroll
    for (int off = 1; off < 32; off <<= 1) {
        int t = __shfl_up_sync(~0u, x, off);
        if (lane >= off) x += t;
    }
    if (lane == 31) warpsum[wid] = x;
    __syncthreads();
    if (wid == 0) {
        int s = warpsum[lane];
#pragma unroll
        for (int off = 1; off < 32; off <<= 1) {
            int t = __shfl_up_sync(~0u, s, off);
            if (lane >= off) s += t;
        }
        warpsum[lane] = s;
    }
    __syncthreads();
    int incl = x + (wid ? warpsum[wid - 1] : 0);
    if (gid < NNODES) g_rowptr[gid] = incl - v;   // local exclusive
    if (tid == 1023) g_blocksum[blockIdx.x] = incl;
}

// ---- phase B: one warp scans the 49 block sums (exclusive) ----
__global__ void scanB_kernel() {
    int lane = threadIdx.x;   // 32
    int v0 = (lane < NBLK) ? g_blocksum[lane] : 0;
    int v1 = (lane + 32 < NBLK) ? g_blocksum[lane + 32] : 0;
    int x0 = v0;
#pragma unroll
    for (int off = 1; off < 32; off <<= 1) {
        int t = __shfl_up_sync(~0u, x0, off);
        if (lane >= off) x0 += t;
    }
    int tot0 = __shfl_sync(~0u, x0, 31);
    int x1 = v1;
#pragma unroll
    for (int off = 1; off < 32; off <<= 1) {
        int t = __shfl_up_sync(~0u, x1, off);
        if (lane >= off) x1 += t;
    }
    if (lane < NBLK) g_blocksum[lane] = x0 - v0;
    if (lane + 32 < NBLK) g_blocksum[lane + 32] = tot0 + x1 - v1;
}

// ---- phase C: add block offsets; init cursor; total is the constant EPRIME ----
__global__ void scanC_kernel() {
    int i = blockIdx.x * blockDim.x + threadIdx.x;
    if (i < NNODES) {
        int r = g_rowptr[i] + g_blocksum[i >> 10];
        g_rowptr[i] = r;
        g_cursor[i] = r;
    }
    if (i == 0) g_rowptr[NNODES] = EPRIME;
}

__global__ void scatter_kernel(const void* __restrict__ ei) {
    bool is64 = (g_flagOr == 0);
    int i = blockIdx.x * blockDim.x + threadIdx.x;
    if (i < EPRIME) {
        int d = (i < NEDGES) ? load_dst(ei, is64, i) : (i - NEDGES);
        int pos = atomicAdd(&g_cursor[d], 1);
        g_eid[pos] = i;
    }
}

// ---------------- SGEMM: C[M,N] = A[M,K] * B[K,N], N = 256 ----------------
// 128x128 block tile, 8x8 per thread via packed fma.rn.f32x2 (FFMA2), BK=8,
// 256 threads, software-pipelined global loads.
// A-tile stored in shared as pre-broadcast (a,a) 64-bit pairs so the inner
// loop needs no per-FMA packing; B pairs come free as consecutive floats.
__global__ void __launch_bounds__(256, 2)
gemm_kernel(const float* __restrict__ A, const float* __restrict__ B,
            float* __restrict__ C, int M, int K, int N) {
    __shared__ unsigned long long As2[8][128];   // broadcast pairs (8 KB)
    __shared__ float Bs[8][128];                 // (4 KB)
    int tid = threadIdx.x;
    int tx = tid & 15, ty = tid >> 4;
    int bm = blockIdx.x * 128, bn = blockIdx.y * 128;

    unsigned long long acc[8][4];
#pragma unroll
    for (int i = 0; i < 8; i++)
#pragma unroll
        for (int j = 0; j < 4; j++) acc[i][j] = 0ull;

    int arow = tid >> 1, acol = (tid & 1) * 4;
    int brow = tid >> 5, bcol = (tid & 31) * 4;
    bool avalid = (bm + arow) < M;
    const float* Aptr = A + (size_t)(bm + arow) * K + acol;
    const float* Bptr = B + (size_t)brow * N + bn + bcol;

    // prologue: load tile 0
    float4 av = avalid ? *(const float4*)(Aptr)
                       : make_float4(0.f, 0.f, 0.f, 0.f);
    float4 bv = *(const float4*)(Bptr);

    for (int k0 = 0; k0 < K; k0 += 8) {
        As2[acol + 0][arow] = bcast_f32x2(av.x);
        As2[acol + 1][arow] = bcast_f32x2(av.y);
        As2[acol + 2][arow] = bcast_f32x2(av.z);
        As2[acol + 3][arow] = bcast_f32x2(av.w);
        *(float4*)&Bs[brow][bcol] = bv;
        __syncthreads();

        // prefetch next tile (overlaps with compute below)
        int k1 = k0 + 8;
        if (k1 < K) {
            av = avalid ? *(const float4*)(Aptr + k1)
                        : make_float4(0.f, 0.f, 0.f, 0.f);
            bv = *(const float4*)(Bptr + (size_t)k1 * N);
        }

#pragma unroll
        for (int kk = 0; kk < 8; kk++) {
            unsigned long long ra[8], rb[4];
            *(ulonglong2*)(ra)     = *(const ulonglong2*)&As2[kk][ty * 8];
            *(ulonglong2*)(ra + 2) = *(const ulonglong2*)&As2[kk][ty * 8 + 2];
            *(ulonglong2*)(ra + 4) = *(const ulonglong2*)&As2[kk][ty * 8 + 4];
            *(ulonglong2*)(ra + 6) = *(const ulonglong2*)&As2[kk][ty * 8 + 6];
            *(ulonglong2*)(rb)     = *(const ulonglong2*)&Bs[kk][tx * 8];
            *(ulonglong2*)(rb + 2) = *(const ulonglong2*)&Bs[kk][tx * 8 + 4];
#pragma unroll
            for (int i = 0; i < 8; i++)
#pragma unroll
                for (int j = 0; j < 4; j++)
                    acc[i][j] = fma_f32x2(ra[i], rb[j], acc[i][j]);
        }
        __syncthreads();
    }
#pragma unroll
    for (int i = 0; i < 8; i++) {
        int gr = bm + ty * 8 + i;
        if (gr < M) {
            const float* f = (const float*)acc[i];
            *(float4*)(C + (size_t)gr * N + bn + tx * 8) =
                make_float4(f[0], f[1], f[2], f[3]);
            *(float4*)(C + (size_t)gr * N + bn + tx * 8 + 4) =
                make_float4(f[4], f[5], f[6], f[7]);
        }
    }
}

// ---------------- per-node attention logits: asrc/adst [N,4] ----------------
__global__ void attn_kernel(const float* __restrict__ h,
                            const float* __restrict__ a_src,
                            const float* __restrict__ a_dst) {
    int warp = (blockIdx.x * blockDim.x + threadIdx.x) >> 5;
    int lane = threadIdx.x & 31;
    if (warp >= NNODES) return;
    const float4* hr = (const float4*)(h + (size_t)warp * CF);
    float4 v0 = hr[lane];        // features 4*lane        (heads 0,1)
    float4 v1 = hr[32 + lane];   // features 128 + 4*lane  (heads 2,3)
    const float4* s4 = (const float4*)a_src;
    const float4* d4 = (const float4*)a_dst;
    float4 sa0 = s4[lane], sa1 = s4[32 + lane];
    float4 da0 = d4[lane], da1 = d4[32 + lane];
    float ps0 = v0.x * sa0.x + v0.y * sa0.y + v0.z * sa0.z + v0.w * sa0.w;
    float ps1 = v1.x * sa1.x + v1.y * sa1.y + v1.z * sa1.z + v1.w * sa1.w;
    float pd0 = v0.x * da0.x + v0.y * da0.y + v0.z * da0.z + v0.w * da0.w;
    float pd1 = v1.x * da1.x + v1.y * da1.y + v1.z * da1.z + v1.w * da1.w;
#pragma unroll
    for (int off = 8; off; off >>= 1) {   // reduce within 16-lane groups
        ps0 += __shfl_xor_sync(~0u, ps0, off);
        ps1 += __shfl_xor_sync(~0u, ps1, off);
        pd0 += __shfl_xor_sync(~0u, pd0, off);
        pd1 += __shfl_xor_sync(~0u, pd1, off);
    }
    if ((lane & 15) == 0) {
        int g = lane >> 4;   // 0: heads 0/2, 1: heads 1/3
        g_asrc[warp * 4 + g]     = ps0;
        g_asrc[warp * 4 + 2 + g] = ps1;
        g_adst[warp * 4 + g]     = pd0;
        g_adst[warp * 4 + 2 + g] = pd1;
    }
}

__device__ __forceinline__ float lrelu(float v) {
    return v > 0.f ? v : NEG_SLOPE * v;
}

// ---------------- edge softmax (warp per dst node, lanes over edges) ----------------
__global__ void softmax_kernel(const void* __restrict__ ei) {
    bool is64 = (g_flagOr == 0);
    int warp = (blockIdx.x * blockDim.x + threadIdx.x) >> 5;
    int lane = threadIdx.x & 31;
    if (warp >= NNODES) return;
    int rs = g_rowptr[warp], re = g_rowptr[warp + 1];
    float4 ad = *(const float4*)(g_adst + warp * 4);

    float4 mx = make_float4(-1e30f, -1e30f, -1e30f, -1e30f);
    for (int i = rs + lane; i < re; i += 32) {
        int e = g_eid[i];
        int s = (e < NEDGES) ? load_src(ei, is64, e) : (e - NEDGES);
        float4 a = *(const float4*)(g_asrc + s * 4);
        mx.x = fmaxf(mx.x, lrelu(a.x + ad.x));
        mx.y = fmaxf(mx.y, lrelu(a.y + ad.y));
        mx.z = fmaxf(mx.z, lrelu(a.z + ad.z));
        mx.w = fmaxf(mx.w, lrelu(a.w + ad.w));
    }
#pragma unroll
    for (int off = 16; off; off >>= 1) {
        mx.x = fmaxf(mx.x, __shfl_xor_sync(~0u, mx.x, off));
        mx.y = fmaxf(mx.y, __shfl_xor_sync(~0u, mx.y, off));
        mx.z = fmaxf(mx.z, __shfl_xor_sync(~0u, mx.z, off));
        mx.w = fmaxf(mx.w, __shfl_xor_sync(~0u, mx.w, off));
    }
    float4 sum = make_float4(0.f, 0.f, 0.f, 0.f);
    for (int i = rs + lane; i < re; i += 32) {
        int e = g_eid[i];
        int s = (e < NEDGES) ? load_src(ei, is64, e) : (e - NEDGES);
        float4 a = *(const float4*)(g_asrc + s * 4);
        float4 ex;
        ex.x = __expf(lrelu(a.x + ad.x) - mx.x);
        ex.y = __expf(lrelu(a.y + ad.y) - mx.y);
        ex.z = __expf(lrelu(a.z + ad.z) - mx.z);
        ex.w = __expf(lrelu(a.w + ad.w) - mx.w);
        sum.x += ex.x; sum.y += ex.y; sum.z += ex.z; sum.w += ex.w;
        *(float4*)(g_ex + (size_t)e * 4) = ex;
    }
#pragma unroll
    for (int off = 16; off; off >>= 1) {
        sum.x += __shfl_xor_sync(~0u, sum.x, off);
        sum.y += __shfl_xor_sync(~0u, sum.y, off);
        sum.z += __shfl_xor_sync(~0u, sum.z, off);
        sum.w += __shfl_xor_sync(~0u, sum.w, off);
    }
    if (lane == 0) {
        float4 rc;
        rc.x = 1.f / (sum.x + 1e-16f);
        rc.y = 1.f / (sum.y + 1e-16f);
        rc.z = 1.f / (sum.z + 1e-16f);
        rc.w = 1.f / (sum.w + 1e-16f);
        *(float4*)(g_rcp + warp * 4) = rc;
    }
}

// ---------------- aggregation (warp per dst node, lanes over 256 features) ----------------
// 4-edge unrolled: 8 independent float4 gathers in flight per lane.
__global__ void agg_kernel(const float* __restrict__ h,
                           const float* __restrict__ bias,
                           float* __restrict__ out,
                           const void* __restrict__ ei) {
    bool is64 = (g_flagOr == 0);
    int warp = (blockIdx.x * blockDim.x + threadIdx.x) >> 5;
    int lane = threadIdx.x & 31;
    if (warp >= NNODES) return;
    int rs = g_rowptr[warp], re = g_rowptr[warp + 1];
    float4 rc = *(const float4*)(g_rcp + warp * 4);
    bool lo = (lane < 16);                 // first float4: heads 0/1, second: heads 2/3
    float rw0 = lo ? rc.x : rc.y;
    float rw1 = lo ? rc.z : rc.w;
    float4 acc0 = make_float4(0.f, 0.f, 0.f, 0.f);
    float4 acc1 = make_float4(0.f, 0.f, 0.f, 0.f);
    int i = rs;
    for (; i + 3 < re; i += 4) {
        int e0 = g_eid[i],     e1 = g_eid[i + 1];
        int e2 = g_eid[i + 2], e3 = g_eid[i + 3];
        int s0 = (e0 < NEDGES) ? load_src(ei, is64, e0) : (e0 - NEDGES);
        int s1 = (e1 < NEDGES) ? load_src(ei, is64, e1) : (e1 - NEDGES);
        int s2 = (e2 < NEDGES) ? load_src(ei, is64, e2) : (e2 - NEDGES);
        int s3 = (e3 < NEDGES) ? load_src(ei, is64, e3) : (e3 - NEDGES);
        float4 x0 = *(const float4*)(g_ex + (size_t)e0 * 4);
        float4 x1 = *(const float4*)(g_ex + (size_t)e1 * 4);
        float4 x2 = *(const float4*)(g_ex + (size_t)e2 * 4);
        float4 x3 = *(const float4*)(g_ex + (size_t)e3 * 4);
        const float4* h0 = (const float4*)(h + (size_t)s0 * CF);
        const float4* h1 = (const float4*)(h + (size_t)s1 * CF);
        const float4* h2 = (const float4*)(h + (size_t)s2 * CF);
        const float4* h3 = (const float4*)(h + (size_t)s3 * CF);
        float4 a0 = h0[lane];      float4 b0 = h0[32 + lane];
        float4 a1 = h1[lane];      float4 b1 = h1[32 + lane];
        float4 a2 = h2[lane];      float4 b2 = h2[32 + lane];
        float4 a3 = h3[lane];      float4 b3 = h3[32 + lane];
        float w00 = (lo ? x0.x : x0.y) * rw0, w01 = (lo ? x0.z : x0.w) * rw1;
        float w10 = (lo ? x1.x : x1.y) * rw0, w11 = (lo ? x1.z : x1.w) * rw1;
        float w20 = (lo ? x2.x : x2.y) * rw0, w21 = (lo ? x2.z : x2.w) * rw1;
        float w30 = (lo ? x3.x : x3.y) * rw0, w31 = (lo ? x3.z : x3.w) * rw1;
        acc0.x += a0.x * w00; acc0.y += a0.y * w00; acc0.z += a0.z * w00; acc0.w += a0.w * w00;
        acc1.x += b0.x * w01; acc1.y += b0.y * w01; acc1.z += b0.z * w01; acc1.w += b0.w * w01;
        acc0.x += a1.x * w10; acc0.y += a1.y * w10; acc0.z += a1.z * w10; acc0.w += a1.w * w10;
        acc1.x += b1.x * w11; acc1.y += b1.y * w11; acc1.z += b1.z * w11; acc1.w += b1.w * w11;
        acc0.x += a2.x * w20; acc0.y += a2.y * w20; acc0.z += a2.z * w20; acc0.w += a2.w * w20;
        acc1.x += b2.x * w21; acc1.y += b2.y * w21; acc1.z += b2.z * w21; acc1.w += b2.w * w21;
        acc0.x += a3.x * w30; acc0.y += a3.y * w30; acc0.z += a3.z * w30; acc0.w += a3.w * w30;
        acc1.x += b3.x * w31; acc1.y += b3.y * w31; acc1.z += b3.z * w31; acc1.w += b3.w * w31;
    }
    for (; i < re; i++) {
        int e = g_eid[i];
        int s = (e < NEDGES) ? load_src(ei, is64, e) : (e - NEDGES);
        float4 xv = *(const float4*)(g_ex + (size_t)e * 4);
        const float4* hr = (const float4*)(h + (size_t)s * CF);
        float4 a = hr[lane];
        float4 b = hr[32 + lane];
        float w0 = (lo ? xv.x : xv.y) * rw0;
        float w1 = (lo ? xv.z : xv.w) * rw1;
        acc0.x += a.x * w0; acc0.y += a.y * w0; acc0.z += a.z * w0; acc0.w += a.w * w0;
        acc1.x += b.x * w1; acc1.y += b.y * w1; acc1.z += b.z * w1; acc1.w += b.w * w1;
    }

    float4 bb0 = ((const float4*)bias)[lane];
    float4 bb1 = ((const float4*)bias)[32 + lane];
    float4 o0, o1;
    o0.x = fmaxf(acc0.x + bb0.x, 0.f);
    o0.y = fmaxf(acc0.y + bb0.y, 0.f);
    o0.z = fmaxf(acc0.z + bb0.z, 0.f);
    o0.w = fmaxf(acc0.w + bb0.w, 0.f);
    o1.x = fmaxf(acc1.x + bb1.x, 0.f);
    o1.y = fmaxf(acc1.y + bb1.y, 0.f);
    o1.z = fmaxf(acc1.z + bb1.z, 0.f);
    o1.w = fmaxf(acc1.w + bb1.w, 0.f);
    float4* orow = (float4*)(out + (size_t)warp * CF);
    orow[lane]      = o0;
    orow[32 + lane] = o1;
}

// ---------------- launcher ----------------
extern "C" void kernel_launch(void* const* d_in, const int* in_sizes, int n_in,
                              void* d_out, int out_size) {
    const float* x   = (const float*)d_in[0];
    const void*  ei  = d_in[1];
    const float* W1  = (const float*)d_in[2];
    const float* as1 = (const float*)d_in[3];
    const float* ad1 = (const float*)d_in[4];
    const float* b1  = (const float*)d_in[5];
    const float* W2  = (const float*)d_in[6];
    const float* as2 = (const float*)d_in[7];
    const float* ad2 = (const float*)d_in[8];
    const float* b2  = (const float*)d_in[9];
    float* out = (float*)d_out;

    float* hp = nullptr;
    float* yp = nullptr;
    cudaGetSymbolAddress((void**)&hp, g_h);
    cudaGetSymbolAddress((void**)&yp, g_y);

    // CSR build (shared by both layers)
    init_kernel<<<(NNODES + 255) / 256, 256>>>();
    detect_kernel<<<256, 256>>>((const int*)ei);
    count_kernel<<<(NEDGES + 255) / 256, 256>>>(ei);
    scanA_kernel<<<NBLK, 1024>>>();
    scanB_kernel<<<1, 32>>>();
    scanC_kernel<<<(NNODES + 255) / 256, 256>>>();
    scatter_kernel<<<(EPRIME + 255) / 256, 256>>>(ei);

    dim3 ggrid((NNODES + 127) / 128, 2);
    int nodeBlocks = (NNODES + 7) / 8;     // 8 warps / block

    // layer 1
    gemm_kernel<<<ggrid, 256>>>(x, W1, hp, NNODES, 128, CF);
    attn_kernel<<<nodeBlocks, 256>>>(hp, as1, ad1);
    softmax_kernel<<<nodeBlocks, 256>>>(ei);
    agg_kernel<<<nodeBlocks, 256>>>(hp, b1, yp, ei);

    // layer 2
    gemm_kernel<<<ggrid, 256>>>(yp, W2, hp, NNODES, CF, CF);
    attn_kernel<<<nodeBlocks, 256>>>(hp, as2, ad2);
    softmax_kernel<<<nodeBlocks, 256>>>(ei);
    agg_kernel<<<nodeBlocks, 256>>>(hp, b2, out, ei);
}

// round 14
// speedup vs baseline: 1.2011x; 1.2011x over previous
#include <cuda_runtime.h>

// Problem constants (MultiLayerGAT: N=50000, E=800000, IN_F=128, HID=64, HEADS=4)
#define NNODES 50000
#define NEDGES 800000
#define EPRIME (NNODES + NEDGES)   // edges + self loops
#define CF 256                     // HEADS * HID
#define NEG_SLOPE 0.2f
#define NBLK ((NNODES + 1023) / 1024)   // 49 scan blocks
#define EXCAP 64                         // cached exp slots per node

// ---------------- device scratch (no allocations allowed) ----------------
__device__ float g_h[(size_t)NNODES * CF];     // current layer features  (51.2 MB)
__device__ float g_y[(size_t)NNODES * CF];     // layer-1 output          (51.2 MB)
__device__ float g_asrc[NNODES * 4];
__device__ float g_adst[NNODES * 4];
__device__ int   g_rowptr[NNODES + 1];
__device__ int   g_cursor[NNODES];
__device__ int   g_eid[EPRIME];
__device__ int   g_blocksum[64];
__device__ int   g_flagOr;                     // 0 => edge_index is int64

// ---------------- edge index accessors (int32/int64 agnostic) ----------------
__device__ __forceinline__ int load_src(const void* ei, bool is64, int e) {
    return is64 ? (int)((const long long*)ei)[e] : ((const int*)ei)[e];
}
__device__ __forceinline__ int load_dst(const void* ei, bool is64, int e) {
    return is64 ? (int)((const long long*)ei)[(size_t)NEDGES + e]
                : ((const int*)ei)[(size_t)NEDGES + e];
}

// ---------------- CSR build ----------------
__global__ void init_kernel() {
    int i = blockIdx.x * blockDim.x + threadIdx.x;
    if (i < NNODES) g_cursor[i] = 1;   // self loop
    if (i == 0) g_flagOr = 0;
}

// OR-reduce the odd 32-bit words of the first E 64-bit slots. If the buffer is
// really int64 (values < 2^31) these are all zero; if it is int32 these words
// are src[1],src[3],... node ids and are virtually certainly nonzero.
__global__ void detect_kernel(const int* __restrict__ ei32) {
    int i = blockIdx.x * blockDim.x + threadIdx.x;
    int stride = gridDim.x * blockDim.x;
    int acc = 0;
    for (; i < NEDGES; i += stride) acc |= ei32[2 * i + 1];
    if (acc) atomicOr(&g_flagOr, 1);
}

__global__ void count_kernel(const void* __restrict__ ei) {
    bool is64 = (g_flagOr == 0);
    int i = blockIdx.x * blockDim.x + threadIdx.x;
    if (i < NEDGES) {
        int d = load_dst(ei, is64, i);
        atomicAdd(&g_cursor[d], 1);
    }
}

// ---- parallel scan, phase A: per-block exclusive scan + block sums ----
__global__ void scanA_kernel() {
    __shared__ int warpsum[32];
    int tid  = threadIdx.x;
    int gid  = blockIdx.x * 1024 + tid;
    int lane = tid & 31, wid = tid >> 5;
    int v = (gid < NNODES) ? g_cursor[gid] : 0;
    int x = v;
#pragma unroll
    for (int off = 1; off < 32; off <<= 1) {
        int t = __shfl_up_sync(~0u, x, off);
        if (lane >= off) x += t;
    }
    if (lane == 31) warpsum[wid] = x;
    __syncthreads();
    if (wid == 0) {
        int s = warpsum[lane];
#pragma unroll
        for (int off = 1; off < 32; off <<= 1) {
            int t = __shfl_up_sync(~0u, s, off);
            if (lane >= off) s += t;
        }
        warpsum[lane] = s;
    }
    __syncthreads();
    int incl = x + (wid ? warpsum[wid - 1] : 0);
    if (gid < NNODES) g_rowptr[gid] = incl - v;   // local exclusive
    if (tid == 1023) g_blocksum[blockIdx.x] = incl;
}

// ---- phase B: one warp scans the 49 block sums (exclusive) ----
__global__ void scanB_kernel() {
    int lane = threadIdx.x;   // 32
    int v0 = (lane < NBLK) ? g_blocksum[lane] : 0;
    int v1 = (lane + 32 < NBLK) ? g_blocksum[lane + 32] : 0;
    int x0 = v0;
#pragma unroll
    for (int off = 1; off < 32; off <<= 1) {
        int t = __shfl_up_sync(~0u, x0, off);
        if (lane >= off) x0 += t;
    }
    int tot0 = __shfl_sync(~0u, x0, 31);
    int x1 = v1;
#pragma unroll
    for (int off = 1; off < 32; off <<= 1) {
        int t = __shfl_up_sync(~0u, x1, off);
        if (lane >= off) x1 += t;
    }
    if (lane < NBLK) g_blocksum[lane] = x0 - v0;
    if (lane + 32 < NBLK) g_blocksum[lane + 32] = tot0 + x1 - v1;
}

// ---- phase C: add block offsets; init cursor; total is the constant EPRIME ----
__global__ void scanC_kernel() {
    int i = blockIdx.x * blockDim.x + threadIdx.x;
    if (i < NNODES) {
        int r = g_rowptr[i] + g_blocksum[i >> 10];
        g_rowptr[i] = r;
        g_cursor[i] = r;
    }
    if (i == 0) g_rowptr[NNODES] = EPRIME;
}

__global__ void scatter_kernel(const void* __restrict__ ei) {
    bool is64 = (g_flagOr == 0);
    int i = blockIdx.x * blockDim.x + threadIdx.x;
    if (i < EPRIME) {
        int d = (i < NEDGES) ? load_dst(ei, is64, i) : (i - NEDGES);
        int pos = atomicAdd(&g_cursor[d], 1);
        g_eid[pos] = i;
    }
}

// ---------------- SGEMM + attention-logit epilogue ----------------
// C[M,N] = A[M,K]*B[K,N]; 128x128 tile, 8x8/thread, BK=8, 256 threads.
// Each block's 128 output columns cover exactly 2 heads (64 features each),
// so the epilogue computes asrc/adst = <h_row, a_vec> for those heads from
// the register accumulators: 8-lane shfl reduce, one writer per (row, head).
__global__ void __launch_bounds__(256, 2)
gemm_attn_kernel(const float* __restrict__ A, const float* __restrict__ B,
                 float* __restrict__ C, int M, int K, int N,
                 const float* __restrict__ a_src, const float* __restrict__ a_dst) {
    __shared__ float As[8][128];
    __shared__ float Bs[8][128];
    int tid = threadIdx.x;
    int tx = tid & 15, ty = tid >> 4;
    int bm = blockIdx.x * 128, bn = blockIdx.y * 128;

    float acc[8][8];
#pragma unroll
    for (int i = 0; i < 8; i++)
#pragma unroll
        for (int j = 0; j < 8; j++) acc[i][j] = 0.f;

    int arow = tid >> 1, acol = (tid & 1) * 4;
    int brow = tid >> 5, bcol = (tid & 31) * 4;
    bool avalid = (bm + arow) < M;
    const float* Aptr = A + (size_t)(bm + arow) * K + acol;
    const float* Bptr = B + (size_t)brow * N + bn + bcol;

    // prologue: load tile 0
    float4 av = avalid ? *(const float4*)(Aptr)
                       : make_float4(0.f, 0.f, 0.f, 0.f);
    float4 bv = *(const float4*)(Bptr);

    for (int k0 = 0; k0 < K; k0 += 8) {
        As[acol + 0][arow] = av.x;
        As[acol + 1][arow] = av.y;
        As[acol + 2][arow] = av.z;
        As[acol + 3][arow] = av.w;
        *(float4*)&Bs[brow][bcol] = bv;
        __syncthreads();

        int k1 = k0 + 8;
        if (k1 < K) {
            av = avalid ? *(const float4*)(Aptr + k1)
                        : make_float4(0.f, 0.f, 0.f, 0.f);
            bv = *(const float4*)(Bptr + (size_t)k1 * N);
        }

#pragma unroll
        for (int kk = 0; kk < 8; kk++) {
            float ra[8], rb[8];
            *(float4*)(ra)     = *(const float4*)&As[kk][ty * 8];
            *(float4*)(ra + 4) = *(const float4*)&As[kk][ty * 8 + 4];
            *(float4*)(rb)     = *(const float4*)&Bs[kk][tx * 8];
            *(float4*)(rb + 4) = *(const float4*)&Bs[kk][tx * 8 + 4];
#pragma unroll
            for (int i = 0; i < 8; i++)
#pragma unroll
                for (int j = 0; j < 8; j++) acc[i][j] += ra[i] * rb[j];
        }
        __syncthreads();
    }

    // attention vectors for this thread's 8 feature columns
    int f0 = bn + tx * 8;          // global feature index of col 0
    int head = f0 >> 6;            // 64 features per head
    float asv[8], adv[8];
#pragma unroll
    for (int j = 0; j < 8; j++) {
        asv[j] = a_src[f0 + j];
        adv[j] = a_dst[f0 + j];
    }

#pragma unroll
    for (int i = 0; i < 8; i++) {
        int gr = bm + ty * 8 + i;
        bool valid = gr < M;
        if (valid) {
            float4 o0 = make_float4(acc[i][0], acc[i][1], acc[i][2], acc[i][3]);
            float4 o1 = make_float4(acc[i][4], acc[i][5], acc[i][6], acc[i][7]);
            *(float4*)(C + (size_t)gr * N + bn + tx * 8)     = o0;
            *(float4*)(C + (size_t)gr * N + bn + tx * 8 + 4) = o1;
        }
        // logits: partial dot over this thread's 8 cols, reduce over the
        // 8-lane tx-subgroup that covers one full head (xor 1/2/4 stays inside)
        float ps = 0.f, pd = 0.f;
#pragma unroll
        for (int j = 0; j < 8; j++) {
            ps += acc[i][j] * asv[j];
            pd += acc[i][j] * adv[j];
        }
#pragma unroll
        for (int off = 1; off < 8; off <<= 1) {
            ps += __shfl_xor_sync(~0u, ps, off);
            pd += __shfl_xor_sync(~0u, pd, off);
        }
        if (valid && (tx & 7) == 0) {
            g_asrc[gr * 4 + head] = ps;
            g_adst[gr * 4 + head] = pd;
        }
    }
}

__device__ __forceinline__ float lrelu(float v) {
    return v > 0.f ? v : NEG_SLOPE * v;
}

// ---------------- fused softmax + aggregation (warp per dst node) ----------------
// pass1: per-head max over edges (lanes over edges)
// pass2: exp-sum; exp values cached in shared (EXCAP slots/node; tail recomputed)
// pass3: 4-edge-unrolled feature gather using cached weights
__global__ void __launch_bounds__(256)
aggfused_kernel(const float* __restrict__ h,
                const float* __restrict__ bias,
                float* __restrict__ out,
                const void* __restrict__ ei) {
    __shared__ float s_ex[8][EXCAP * 4];   // 8 KB: per-warp exp cache
    bool is64 = (g_flagOr == 0);
    int wlocal = threadIdx.x >> 5;
    int warp = blockIdx.x * 8 + wlocal;
    int lane = threadIdx.x & 31;
    if (warp >= NNODES) return;
    int rs = g_rowptr[warp], re = g_rowptr[warp + 1];
    float4 ad = *(const float4*)(g_adst + warp * 4);

    // ---- pass 1: max per head ----
    float4 mx = make_float4(-1e30f, -1e30f, -1e30f, -1e30f);
    for (int i = rs + lane; i < re; i += 32) {
        int e = g_eid[i];
        int s = (e < NEDGES) ? load_src(ei, is64, e) : (e - NEDGES);
        float4 a = *(const float4*)(g_asrc + s * 4);
        mx.x = fmaxf(mx.x, lrelu(a.x + ad.x));
        mx.y = fmaxf(mx.y, lrelu(a.y + ad.y));
        mx.z = fmaxf(mx.z, lrelu(a.z + ad.z));
        mx.w = fmaxf(mx.w, lrelu(a.w + ad.w));
    }
#pragma unroll
    for (int off = 16; off; off >>= 1) {
        mx.x = fmaxf(mx.x, __shfl_xor_sync(~0u, mx.x, off));
        mx.y = fmaxf(mx.y, __shfl_xor_sync(~0u, mx.y, off));
        mx.z = fmaxf(mx.z, __shfl_xor_sync(~0u, mx.z, off));
        mx.w = fmaxf(mx.w, __shfl_xor_sync(~0u, mx.w, off));
    }

    // ---- pass 2: exp + sum, cache exp in shared ----
    float4 sum = make_float4(0.f, 0.f, 0.f, 0.f);
    for (int i = rs + lane; i < re; i += 32) {
        int e = g_eid[i];
        int s = (e < NEDGES) ? load_src(ei, is64, e) : (e - NEDGES);
        float4 a = *(const float4*)(g_asrc + s * 4);
        float4 ex;
        ex.x = __expf(lrelu(a.x + ad.x) - mx.x);
        ex.y = __expf(lrelu(a.y + ad.y) - mx.y);
        ex.z = __expf(lrelu(a.z + ad.z) - mx.z);
        ex.w = __expf(lrelu(a.w + ad.w) - mx.w);
        sum.x += ex.x; sum.y += ex.y; sum.z += ex.z; sum.w += ex.w;
        int slot = i - rs;
        if (slot < EXCAP) *(float4*)&s_ex[wlocal][slot * 4] = ex;
    }
#pragma unroll
    for (int off = 16; off; off >>= 1) {
        sum.x += __shfl_xor_sync(~0u, sum.x, off);
        sum.y += __shfl_xor_sync(~0u, sum.y, off);
        sum.z += __shfl_xor_sync(~0u, sum.z, off);
        sum.w += __shfl_xor_sync(~0u, sum.w, off);
    }
    float4 rc;
    rc.x = 1.f / (sum.x + 1e-16f);
    rc.y = 1.f / (sum.y + 1e-16f);
    rc.z = 1.f / (sum.z + 1e-16f);
    rc.w = 1.f / (sum.w + 1e-16f);
    __syncwarp();

    // ---- pass 3: weighted feature gather (4-edge unrolled) ----
    bool lo = (lane < 16);                 // first float4: heads 0/1, second: heads 2/3
    float rw0 = lo ? rc.x : rc.y;
    float rw1 = lo ? rc.z : rc.w;

    auto getex = [&](int i, int s) -> float4 {
        int slot = i - rs;
        if (slot < EXCAP) return *(const float4*)&s_ex[wlocal][slot * 4];
        float4 a = *(const float4*)(g_asrc + s * 4);   // rare tail: recompute
        float4 ex;
        ex.x = __expf(lrelu(a.x + ad.x) - mx.x);
        ex.y = __expf(lrelu(a.y + ad.y) - mx.y);
        ex.z = __expf(lrelu(a.z + ad.z) - mx.z);
        ex.w = __expf(lrelu(a.w + ad.w) - mx.w);
        return ex;
    };

    float4 acc0 = make_float4(0.f, 0.f, 0.f, 0.f);
    float4 acc1 = make_float4(0.f, 0.f, 0.f, 0.f);
    int i = rs;
    for (; i + 3 < re; i += 4) {
        int e0 = g_eid[i],     e1 = g_eid[i + 1];
        int e2 = g_eid[i + 2], e3 = g_eid[i + 3];
        int s0 = (e0 < NEDGES) ? load_src(ei, is64, e0) : (e0 - NEDGES);
        int s1 = (e1 < NEDGES) ? load_src(ei, is64, e1) : (e1 - NEDGES);
        int s2 = (e2 < NEDGES) ? load_src(ei, is64, e2) : (e2 - NEDGES);
        int s3 = (e3 < NEDGES) ? load_src(ei, is64, e3) : (e3 - NEDGES);
        float4 x0 = getex(i, s0);
        float4 x1 = getex(i + 1, s1);
        float4 x2 = getex(i + 2, s2);
        float4 x3 = getex(i + 3, s3);
        const float4* h0 = (const float4*)(h + (size_t)s0 * CF);
        const float4* h1 = (const float4*)(h + (size_t)s1 * CF);
        const float4* h2 = (const float4*)(h + (size_t)s2 * CF);
        const float4* h3 = (const float4*)(h + (size_t)s3 * CF);
        float4 a0 = h0[lane];      float4 b0 = h0[32 + lane];
        float4 a1 = h1[lane];      float4 b1 = h1[32 + lane];
        float4 a2 = h2[lane];      float4 b2 = h2[32 + lane];
        float4 a3 = h3[lane];      float4 b3 = h3[32 + lane];
        float w00 = (lo ? x0.x : x0.y) * rw0, w01 = (lo ? x0.z : x0.w) * rw1;
        float w10 = (lo ? x1.x : x1.y) * rw0, w11 = (lo ? x1.z : x1.w) * rw1;
        float w20 = (lo ? x2.x : x2.y) * rw0, w21 = (lo ? x2.z : x2.w) * rw1;
        float w30 = (lo ? x3.x : x3.y) * rw0, w31 = (lo ? x3.z : x3.w) * rw1;
        acc0.x += a0.x * w00; acc0.y += a0.y * w00; acc0.z += a0.z * w00; acc0.w += a0.w * w00;
        acc1.x += b0.x * w01; acc1.y += b0.y * w01; acc1.z += b0.z * w01; acc1.w += b0.w * w01;
        acc0.x += a1.x * w10; acc0.y += a1.y * w10; acc0.z += a1.z * w10; acc0.w += a1.w * w10;
        acc1.x += b1.x * w11; acc1.y += b1.y * w11; acc1.z += b1.z * w11; acc1.w += b1.w * w11;
        acc0.x += a2.x * w20; acc0.y += a2.y * w20; acc0.z += a2.z * w20; acc0.w += a2.w * w20;
        acc1.x += b2.x * w21; acc1.y += b2.y * w21; acc1.z += b2.z * w21; acc1.w += b2.w * w21;
        acc0.x += a3.x * w30; acc0.y += a3.y * w30; acc0.z += a3.z * w30; acc0.w += a3.w * w30;
        acc1.x += b3.x * w31; acc1.y += b3.y * w31; acc1.z += b3.z * w31; acc1.w += b3.w * w31;
    }
    for (; i < re; i++) {
        int e = g_eid[i];
        int s = (e < NEDGES) ? load_src(ei, is64, e) : (e - NEDGES);
        float4 xv = getex(i, s);
        const float4* hr = (const float4*)(h + (size_t)s * CF);
        float4 a = hr[lane];
        float4 b = hr[32 + lane];
        float w0 = (lo ? xv.x : xv.y) * rw0;
        float w1 = (lo ? xv.z : xv.w) * rw1;
        acc0.x += a.x * w0; acc0.y += a.y * w0; acc0.z += a.z * w0; acc0.w += a.w * w0;
        acc1.x += b.x * w1; acc1.y += b.y * w1; acc1.z += b.z * w1; acc1.w += b.w * w1;
    }

    float4 bb0 = ((const float4*)bias)[lane];
    float4 bb1 = ((const float4*)bias)[32 + lane];
    float4 o0, o1;
    o0.x = fmaxf(acc0.x + bb0.x, 0.f);
    o0.y = fmaxf(acc0.y + bb0.y, 0.f);
    o0.z = fmaxf(acc0.z + bb0.z, 0.f);
    o0.w = fmaxf(acc0.w + bb0.w, 0.f);
    o1.x = fmaxf(acc1.x + bb1.x, 0.f);
    o1.y = fmaxf(acc1.y + bb1.y, 0.f);
    o1.z = fmaxf(acc1.z + bb1.z, 0.f);
    o1.w = fmaxf(acc1.w + bb1.w, 0.f);
    float4* orow = (float4*)(out + (size_t)warp * CF);
    orow[lane]      = o0;
    orow[32 + lane] = o1;
}

// ---------------- launcher ----------------
extern "C" void kernel_launch(void* const* d_in, const int* in_sizes, int n_in,
                              void* d_out, int out_size) {
    const float* x   = (const float*)d_in[0];
    const void*  ei  = d_in[1];
    const float* W1  = (const float*)d_in[2];
    const float* as1 = (const float*)d_in[3];
    const float* ad1 = (const float*)d_in[4];
    const float* b1  = (const float*)d_in[5];
    const float* W2  = (const float*)d_in[6];
    const float* as2 = (const float*)d_in[7];
    const float* ad2 = (const float*)d_in[8];
    const float* b2  = (const float*)d_in[9];
    float* out = (float*)d_out;

    float* hp = nullptr;
    float* yp = nullptr;
    cudaGetSymbolAddress((void**)&hp, g_h);
    cudaGetSymbolAddress((void**)&yp, g_y);

    // CSR build (shared by both layers)
    init_kernel<<<(NNODES + 255) / 256, 256>>>();
    detect_kernel<<<256, 256>>>((const int*)ei);
    count_kernel<<<(NEDGES + 255) / 256, 256>>>(ei);
    scanA_kernel<<<NBLK, 1024>>>();
    scanB_kernel<<<1, 32>>>();
    scanC_kernel<<<(NNODES + 255) / 256, 256>>>();
    scatter_kernel<<<(EPRIME + 255) / 256, 256>>>(ei);

    dim3 ggrid((NNODES + 127) / 128, 2);
    int nodeBlocks = (NNODES + 7) / 8;     // 8 warps / block

    // layer 1
    gemm_attn_kernel<<<ggrid, 256>>>(x, W1, hp, NNODES, 128, CF, as1, ad1);
    aggfused_kernel<<<nodeBlocks, 256>>>(hp, b1, yp, ei);

    // layer 2
    gemm_attn_kernel<<<ggrid, 256>>>(yp, W2, hp, NNODES, CF, CF, as2, ad2);
    aggfused_kernel<<<nodeBlocks, 256>>>(hp, b2, out, ei);
}